// round 6
// baseline (speedup 1.0000x reference)
#include <cuda_runtime.h>
#include <cuda_bf16.h>
#include <math.h>
#include <stdint.h>

// Problem constants
#define B_    2
#define Q_    75
#define WAY_  5
#define SHOT_ 5
#define HW_   100
#define C_    640
#define NK_   5

#define MROWS (Q_*HW_)        // 7500 query patches per b
#define NROWS (WAY_*HW_)      // 500 support patches per group
#define NGRP  (B_*SHOT_)      // 10 groups
#define NQTOT (B_*MROWS)      // 15000
#define NSTOT (NGRP*NROWS)    // 5000

// Normalized bf16 descriptors (static device scratch — allocation-free)
__device__ __nv_bfloat16 g_q16[(size_t)NQTOT * C_];
__device__ __nv_bfloat16 g_s16[(size_t)NSTOT * C_];

__device__ __forceinline__ uint32_t smem_u32(const void* p) {
    uint32_t a;
    asm("{ .reg .u64 t; cvta.to.shared.u64 t, %1; cvt.u32.u64 %0, t; }"
        : "=r"(a) : "l"(p));
    return a;
}

#define SWZ128(o) ((o) ^ (((o) >> 3) & 0x70))

// ---------------------------------------------------------------------------
// Kernel 1: L2-normalize each 640-dim descriptor, cast to bf16.
// One warp per row (20000 rows). Block 0 also zeroes the 750-float output.
// ---------------------------------------------------------------------------
__global__ void normalize_kernel(const float* __restrict__ q,
                                 const float* __restrict__ s,
                                 float* __restrict__ out) {
    if (blockIdx.x == 0 && threadIdx.x < 250) {
        #pragma unroll
        for (int j = 0; j < 3; j++) out[threadIdx.x + 250 * j] = 0.f;
    }

    int warp = (blockIdx.x * blockDim.x + threadIdx.x) >> 5;
    int lane = threadIdx.x & 31;
    if (warp >= NQTOT + NSTOT) return;

    const float* src;
    __nv_bfloat16* dst;
    if (warp < NQTOT) {
        src = q + (size_t)warp * C_;
        dst = g_q16 + (size_t)warp * C_;
    } else {
        int r = warp - NQTOT;
        src = s + (size_t)r * C_;
        dst = g_s16 + (size_t)r * C_;
    }

    const float4* p4 = (const float4*)src;
    float4 v[5];
    float acc = 0.f;
    #pragma unroll
    for (int t = 0; t < 5; t++) {
        v[t] = p4[lane + 32 * t];
        acc += v[t].x * v[t].x + v[t].y * v[t].y + v[t].z * v[t].z + v[t].w * v[t].w;
    }
    #pragma unroll
    for (int o = 16; o; o >>= 1) acc += __shfl_xor_sync(0xFFFFFFFFu, acc, o);
    float inv = rsqrtf(acc);

    #pragma unroll
    for (int t = 0; t < 5; t++) {
        __nv_bfloat162 lo = __float22bfloat162_rn(make_float2(v[t].x * inv, v[t].y * inv));
        __nv_bfloat162 hi = __float22bfloat162_rn(make_float2(v[t].z * inv, v[t].w * inv));
        uint2 pack;
        pack.x = *(uint32_t*)&lo;
        pack.y = *(uint32_t*)&hi;
        *(uint2*)(dst + (size_t)(lane + 32 * t) * 4) = pack;
    }
}

// ---------------------------------------------------------------------------
// Kernel 2: fused bf16 HMMA GEMM (128 x 512 x 640) + streaming top-5 + reduce.
// grid = (59 M-tiles, 10 groups), 256 threads (8 warps as 4x2), 2 CTAs/SM.
// 40 flattened stages (4 N-chunks x 10 K-chunks), 3-deep cp.async pipeline,
// ONE __syncthreads per stage, 2 loads always in flight.
// ---------------------------------------------------------------------------
#define BM   128
#define BNC  128           // N chunk
#define BK   64            // K chunk (64 bf16 = 128B rows, SW128)
#define NKC  (C_/BK)       // 10
#define NNC  4             // N chunks (covers 512 padded)
#define NSTG (NNC*NKC)     // 40 pipeline stages

#define STG_BYTES 32768
#define SA_OFF(buf) ((buf) * STG_BYTES)
#define SB_OFF(buf) ((buf) * STG_BYTES + 16384)
#define SMEM_TOTAL  (3 * STG_BYTES)              // 98304

__global__ __launch_bounds__(256, 2)
void fused_gemm_topk_kernel(float* __restrict__ out) {
    extern __shared__ __align__(1024) char smem[];
    const uint32_t sbase = smem_u32(smem);
    const int tid   = threadIdx.x;
    const int lane  = tid & 31;
    const int wid   = tid >> 5;
    const int warpM = wid >> 1;      // 0..3
    const int warpN = wid & 1;       // 0..1

    const int mBlock = blockIdx.x * BM;
    const int z   = blockIdx.y;      // b*5 + group
    const int b   = z / SHOT_;
    const int grp = z % SHOT_;

    const __nv_bfloat16* gA = g_q16 + (size_t)b * MROWS * C_;
    const __nv_bfloat16* gB = g_s16 + (size_t)z * NROWS * C_;

    // running top-5 per owned row: rr -> row = warpM*32 + rr*8 + lane/4
    float t5[4][5];
    #pragma unroll
    for (int r = 0; r < 4; r++)
        #pragma unroll
        for (int j = 0; j < 5; j++) t5[r][j] = -INFINITY;

    // stage loader: stage s = cb*NKC + kc. A 128x64 bf16 + B 128x64 bf16.
    auto load_stage = [&](int s, int buf) {
        const int cb = s / NKC;
        const int kc = s - cb * NKC;
        #pragma unroll
        for (int t = 0; t < 4; t++) {
            int u = tid + t * 256;
            int r = u >> 3, seg = u & 7;
            int gm = mBlock + r;
            uint32_t dst = sbase + SA_OFF(buf) + SWZ128(r * 128 + seg * 16);
            const char* src = (const char*)gA
                + ((size_t)(gm < MROWS ? gm : 0) * C_ + kc * BK) * 2 + seg * 16;
            int sz = (gm < MROWS) ? 16 : 0;
            asm volatile("cp.async.cg.shared.global [%0], [%1], 16, %2;"
                         :: "r"(dst), "l"(src), "r"(sz));
        }
        #pragma unroll
        for (int t = 0; t < 4; t++) {
            int u = tid + t * 256;
            int r = u >> 3, seg = u & 7;
            int gn = cb * BNC + r;
            uint32_t dst = sbase + SB_OFF(buf) + SWZ128(r * 128 + seg * 16);
            const char* src = (const char*)gB
                + ((size_t)(gn < NROWS ? gn : 0) * C_ + kc * BK) * 2 + seg * 16;
            int sz = (gn < NROWS) ? 16 : 0;
            asm volatile("cp.async.cg.shared.global [%0], [%1], 16, %2;"
                         :: "r"(dst), "l"(src), "r"(sz));
        }
        asm volatile("cp.async.commit_group;" ::: "memory");
    };

    float acc[2][8][4];
    #pragma unroll
    for (int mt = 0; mt < 2; mt++)
        #pragma unroll
        for (int nt = 0; nt < 8; nt++)
            #pragma unroll
            for (int c = 0; c < 4; c++) acc[mt][nt][c] = 0.f;

    load_stage(0, 0);
    load_stage(1, 1);

    int buf = 0;           // rotating 0,1,2
    #pragma unroll 1
    for (int s = 0; s < NSTG; s++) {
        const int cb = s / NKC;
        const int kc = s - cb * NKC;

        // wait for stage s's group (keep s+1's group in flight if it exists)
        if (s + 1 < NSTG) {
            asm volatile("cp.async.wait_group 1;" ::: "memory");
        } else {
            asm volatile("cp.async.wait_group 0;" ::: "memory");
        }
        __syncthreads();   // publish stage s data; retire stage s-1 reads

        // issue load of stage s+2 into the buffer freed by stage s-1
        if (s + 2 < NSTG) {
            int nb = buf + 2; if (nb >= 3) nb -= 3;
            load_stage(s + 2, nb);
        }

        const uint32_t sA = sbase + SA_OFF(buf);
        const uint32_t sB = sbase + SB_OFF(buf);

        #pragma unroll
        for (int ks = 0; ks < 4; ks++) {
            uint32_t a[2][4];
            #pragma unroll
            for (int mt = 0; mt < 2; mt++) {
                int row = warpM * 32 + mt * 16 + (lane & 15);
                uint32_t ad = sA + SWZ128(row * 128 + ks * 32 + (lane >> 4) * 16);
                asm volatile(
                    "ldmatrix.sync.aligned.m8n8.x4.shared.b16 {%0,%1,%2,%3}, [%4];"
                    : "=r"(a[mt][0]), "=r"(a[mt][1]), "=r"(a[mt][2]), "=r"(a[mt][3])
                    : "r"(ad));
            }
            uint32_t bq[4][4];
            #pragma unroll
            for (int nt2 = 0; nt2 < 4; nt2++) {
                int qd = lane >> 3;          // matrix index 0..3
                int rr = lane & 7;
                int row = warpN * 64 + nt2 * 16 + (qd >> 1) * 8 + rr;
                uint32_t bd = sB + SWZ128(row * 128 + ks * 32 + (qd & 1) * 16);
                asm volatile(
                    "ldmatrix.sync.aligned.m8n8.x4.shared.b16 {%0,%1,%2,%3}, [%4];"
                    : "=r"(bq[nt2][0]), "=r"(bq[nt2][1]), "=r"(bq[nt2][2]), "=r"(bq[nt2][3])
                    : "r"(bd));
            }
            #pragma unroll
            for (int mt = 0; mt < 2; mt++)
                #pragma unroll
                for (int nt = 0; nt < 8; nt++) {
                    uint32_t b0 = bq[nt >> 1][(nt & 1) * 2 + 0];
                    uint32_t b1 = bq[nt >> 1][(nt & 1) * 2 + 1];
                    asm volatile(
                        "mma.sync.aligned.m16n8k16.row.col.f32.bf16.bf16.f32 "
                        "{%0,%1,%2,%3}, {%4,%5,%6,%7}, {%8,%9}, {%0,%1,%2,%3};"
                        : "+f"(acc[mt][nt][0]), "+f"(acc[mt][nt][1]),
                          "+f"(acc[mt][nt][2]), "+f"(acc[mt][nt][3])
                        : "r"(a[mt][0]), "r"(a[mt][1]), "r"(a[mt][2]), "r"(a[mt][3]),
                          "r"(b0), "r"(b1));
                }
        }

        // end of an N-chunk: fold acc into per-row top-5 (register-only,
        // overlaps with the 2 loads already in flight), reset acc.
        if (kc == NKC - 1) {
            const int colBase = cb * BNC + warpN * 64 + (lane & 3) * 2;
            #pragma unroll
            for (int mt = 0; mt < 2; mt++)
                #pragma unroll
                for (int c2 = 0; c2 < 2; c2++)
                    #pragma unroll
                    for (int nt = 0; nt < 8; nt++)
                        #pragma unroll
                        for (int c1 = 0; c1 < 2; c1++) {
                            float v = acc[mt][nt][c2 * 2 + c1];
                            int col = colBase + nt * 8 + c1;
                            if (col < NROWS && v > t5[mt * 2 + c2][4]) {
                                t5[mt * 2 + c2][4] = v;
                                #pragma unroll
                                for (int j = 4; j > 0; j--) {
                                    if (t5[mt * 2 + c2][j] > t5[mt * 2 + c2][j - 1]) {
                                        float x = t5[mt * 2 + c2][j];
                                        t5[mt * 2 + c2][j] = t5[mt * 2 + c2][j - 1];
                                        t5[mt * 2 + c2][j - 1] = x;
                                    }
                                }
                            }
                        }
            #pragma unroll
            for (int mt = 0; mt < 2; mt++)
                #pragma unroll
                for (int nt = 0; nt < 8; nt++)
                    #pragma unroll
                    for (int c = 0; c < 4; c++) acc[mt][nt][c] = 0.f;
        }

        if (++buf == 3) buf = 0;
    }

    // dump per-thread top-5s: row x 8 contributors x 5 (20KB, reuses smem)
    __syncthreads();
    float* dump = (float*)smem;
    const int slot = warpN * 4 + (lane & 3);
    #pragma unroll
    for (int rr = 0; rr < 4; rr++) {
        int row = warpM * 32 + rr * 8 + (lane >> 2);
        #pragma unroll
        for (int j = 0; j < 5; j++)
            dump[row * 40 + slot * 5 + j] = t5[rr][j];
    }
    __syncthreads();

    // final: one thread per row merges 40 candidates -> top-5 mean -> atomicAdd
    if (tid < BM) {
        int gm = mBlock + tid;
        if (gm < MROWS) {
            const float* vals = dump + tid * 40;
            float s0 = -INFINITY, s1 = -INFINITY, s2 = -INFINITY,
                  s3 = -INFINITY, s4 = -INFINITY;
            #pragma unroll
            for (int i = 0; i < 40; i++) {
                float v = vals[i];
                if (v > s4) {
                    s4 = v;
                    if (s4 > s3) { float x = s4; s4 = s3; s3 = x; }
                    if (s3 > s2) { float x = s3; s3 = s2; s2 = x; }
                    if (s2 > s1) { float x = s2; s2 = s1; s1 = x; }
                    if (s1 > s0) { float x = s1; s1 = s0; s0 = x; }
                }
            }
            int q = gm / HW_;
            float val = (s0 + s1 + s2 + s3 + s4) * (1.0f / NK_);
            atomicAdd(&out[(b * Q_ + q) * WAY_ + grp], val);
        }
    }
}

// ---------------------------------------------------------------------------
extern "C" void kernel_launch(void* const* d_in, const int* in_sizes, int n_in,
                              void* d_out, int out_size) {
    const float* input1 = (const float*)d_in[0];   // [2,75,10,10,640]
    const float* input2 = (const float*)d_in[1];   // [2,5,5,10,10,640]
    float* out = (float*)d_out;                    // [2,75,5] = 750

    cudaFuncSetAttribute(fused_gemm_topk_kernel,
                         cudaFuncAttributeMaxDynamicSharedMemorySize, SMEM_TOTAL);

    normalize_kernel<<<(NQTOT + NSTOT + 7) / 8, 256>>>(input1, input2, out);

    dim3 grid((MROWS + BM - 1) / BM, NGRP);        // (59, 10)
    fused_gemm_topk_kernel<<<grid, 256, SMEM_TOTAL>>>(out);
}

// round 7
// speedup vs baseline: 1.1095x; 1.1095x over previous
#include <cuda_runtime.h>
#include <cuda_bf16.h>
#include <math.h>
#include <stdint.h>

// Problem constants
#define B_    2
#define Q_    75
#define WAY_  5
#define SHOT_ 5
#define HW_   100
#define C_    640
#define NK_   5

#define MROWS (Q_*HW_)        // 7500 query patches per b
#define NROWS (WAY_*HW_)      // 500 support patches per group
#define NGRP  (B_*SHOT_)      // 10 groups
#define NQTOT (B_*MROWS)      // 15000
#define NSTOT (NGRP*NROWS)    // 5000

// Normalized bf16 descriptors (static device scratch — allocation-free)
__device__ __nv_bfloat16 g_q16[(size_t)NQTOT * C_];
__device__ __nv_bfloat16 g_s16[(size_t)NSTOT * C_];

__device__ __forceinline__ uint32_t smem_u32(const void* p) {
    uint32_t a;
    asm("{ .reg .u64 t; cvta.to.shared.u64 t, %1; cvt.u32.u64 %0, t; }"
        : "=r"(a) : "l"(p));
    return a;
}

#define SWZ128(o) ((o) ^ (((o) >> 3) & 0x70))

// ---------------------------------------------------------------------------
// Kernel 1: L2-normalize each 640-dim descriptor, cast to bf16.
// One warp per row (20000 rows). Block 0 also zeroes the 750-float output.
// ---------------------------------------------------------------------------
__global__ void normalize_kernel(const float* __restrict__ q,
                                 const float* __restrict__ s,
                                 float* __restrict__ out) {
    if (blockIdx.x == 0 && threadIdx.x < 250) {
        #pragma unroll
        for (int j = 0; j < 3; j++) out[threadIdx.x + 250 * j] = 0.f;
    }

    int warp = (blockIdx.x * blockDim.x + threadIdx.x) >> 5;
    int lane = threadIdx.x & 31;
    if (warp >= NQTOT + NSTOT) return;

    const float* src;
    __nv_bfloat16* dst;
    if (warp < NQTOT) {
        src = q + (size_t)warp * C_;
        dst = g_q16 + (size_t)warp * C_;
    } else {
        int r = warp - NQTOT;
        src = s + (size_t)r * C_;
        dst = g_s16 + (size_t)r * C_;
    }

    const float4* p4 = (const float4*)src;
    float4 v[5];
    float acc = 0.f;
    #pragma unroll
    for (int t = 0; t < 5; t++) {
        v[t] = p4[lane + 32 * t];
        acc += v[t].x * v[t].x + v[t].y * v[t].y + v[t].z * v[t].z + v[t].w * v[t].w;
    }
    #pragma unroll
    for (int o = 16; o; o >>= 1) acc += __shfl_xor_sync(0xFFFFFFFFu, acc, o);
    float inv = rsqrtf(acc);

    #pragma unroll
    for (int t = 0; t < 5; t++) {
        __nv_bfloat162 lo = __float22bfloat162_rn(make_float2(v[t].x * inv, v[t].y * inv));
        __nv_bfloat162 hi = __float22bfloat162_rn(make_float2(v[t].z * inv, v[t].w * inv));
        uint2 pack;
        pack.x = *(uint32_t*)&lo;
        pack.y = *(uint32_t*)&hi;
        *(uint2*)(dst + (size_t)(lane + 32 * t) * 4) = pack;
    }
}

// ---------------------------------------------------------------------------
// Kernel 2: fused bf16 HMMA GEMM (128 x 512 x 640) + streaming top-5 + reduce.
// grid = (59 M-tiles, 10 groups), 256 threads (8 warps as 4x2), 2 CTAs/SM.
// 40 flattened stages, 3-deep cp.async pipeline, incremental pointers and
// XOR-swizzle ldmatrix addressing to minimize per-stage ALU.
// ---------------------------------------------------------------------------
#define BM   128
#define BNC  128           // N chunk
#define BK   64            // K chunk (64 bf16 = 128B rows, SW128)
#define NKC  (C_/BK)       // 10
#define NNC  4             // N chunks (covers 512 padded)
#define NSTG (NNC*NKC)     // 40 pipeline stages

#define STG_BYTES 32768
#define SMEM_TOTAL (3 * STG_BYTES)               // 98304

// cp.async with compile-time slot offsets (dst shared [reg+imm], src global [reg+imm])
#define CPA(dstReg, dimm, srcReg, simm, sz) \
    asm volatile("cp.async.cg.shared.global [%0 + %1], [%2 + %3], 16, %4;" \
        :: "r"(dstReg), "n"(dimm), "l"(srcReg), "n"(simm), "r"(sz))

__global__ __launch_bounds__(256, 2)
void fused_gemm_topk_kernel(float* __restrict__ out) {
    extern __shared__ __align__(1024) char smem[];
    const uint32_t sbase = smem_u32(smem);
    const int tid   = threadIdx.x;
    const int lane  = tid & 31;
    const int wid   = tid >> 5;
    const int warpM = wid >> 1;      // 0..3
    const int warpN = wid & 1;       // 0..1

    const int mBlock = blockIdx.x * BM;
    const int z   = blockIdx.y;      // b*5 + group
    const int b   = z / SHOT_;
    const int grp = z % SHOT_;

    const __nv_bfloat16* gA = g_q16 + (size_t)b * MROWS * C_;
    const __nv_bfloat16* gB = g_s16 + (size_t)z * NROWS * C_;

    // ---- precomputed loader state ----
    const int r0  = tid >> 3;        // 0..31 (row within 32-row slab)
    const int seg = tid & 7;         // 16B segment
    const uint32_t off0 = SWZ128(r0 * 128 + seg * 16);  // slot t adds t*4096

    // per-thread global pointers (slot t adds t*40960 = 32 rows * 1280B)
    const char* pA = (const char*)gA + (size_t)(mBlock + r0) * (C_ * 2) + seg * 16;
    const char* pB = (const char*)gB + (size_t)r0 * (C_ * 2) + seg * 16;

    // A row-validity (constant): sz per slot
    int szA0 = (mBlock + r0       < MROWS) ? 16 : 0;
    int szA1 = (mBlock + r0 + 32  < MROWS) ? 16 : 0;
    int szA2 = (mBlock + r0 + 64  < MROWS) ? 16 : 0;
    int szA3 = (mBlock + r0 + 96  < MROWS) ? 16 : 0;

    int lkc = 0, lcb = 0;            // loader stage state

    auto issue_load = [&](int bufIdx) {
        const uint32_t dstA = sbase + bufIdx * STG_BYTES + off0;
        // B validity: rows cb*128 + r0 + 32t < 500  (only cb=3 clips)
        const int thr = (lcb == 3) ? 116 : 128;
        int szB0 = (r0       < thr) ? 16 : 0;
        int szB1 = (r0 + 32  < thr) ? 16 : 0;
        int szB2 = (r0 + 64  < thr) ? 16 : 0;
        int szB3 = (r0 + 96  < thr) ? 16 : 0;
        CPA(dstA, 0,     pA, 0,      szA0);
        CPA(dstA, 4096,  pA, 40960,  szA1);
        CPA(dstA, 8192,  pA, 81920,  szA2);
        CPA(dstA, 12288, pA, 122880, szA3);
        CPA(dstA, 16384, pB, 0,      szB0);
        CPA(dstA, 20480, pB, 40960,  szB1);
        CPA(dstA, 24576, pB, 81920,  szB2);
        CPA(dstA, 28672, pB, 122880, szB3);
        asm volatile("cp.async.commit_group;" ::: "memory");
        // advance loader state
        if (lkc == NKC - 1) {
            lkc = 0; lcb++;
            pA -= (NKC - 1) * 128;                       // back to kc=0
            pB += BNC * (C_ * 2) - (NKC - 1) * 128;      // next row block, kc=0
        } else {
            lkc++; pA += 128; pB += 128;
        }
    };

    // ---- precomputed ldmatrix bases (XOR with ks<<5 per step) ----
    uint32_t baseA[2], baseB[4];
    #pragma unroll
    for (int mt = 0; mt < 2; mt++) {
        int row = warpM * 32 + mt * 16 + (lane & 15);
        baseA[mt] = SWZ128((uint32_t)(row * 128 + (lane >> 4) * 16));
    }
    {
        int qd = lane >> 3, rr = lane & 7;
        #pragma unroll
        for (int nt2 = 0; nt2 < 4; nt2++) {
            int row = warpN * 64 + nt2 * 16 + (qd >> 1) * 8 + rr;
            baseB[nt2] = SWZ128((uint32_t)(row * 128 + (qd & 1) * 16));
        }
    }

    // running top-5 per owned row: rr -> row = warpM*32 + rr*8 + lane/4
    float t5[4][5];
    #pragma unroll
    for (int r = 0; r < 4; r++)
        #pragma unroll
        for (int j = 0; j < 5; j++) t5[r][j] = -INFINITY;

    float acc[2][8][4];
    #pragma unroll
    for (int mt = 0; mt < 2; mt++)
        #pragma unroll
        for (int nt = 0; nt < 8; nt++)
            #pragma unroll
            for (int c = 0; c < 4; c++) acc[mt][nt][c] = 0.f;

    issue_load(0);
    issue_load(1);

    int buf = 0;                       // rotating 0,1,2
    int ckc = 0, ccb = 0;              // compute stage state
    #pragma unroll 1
    for (int s = 0; s < NSTG; s++) {
        if (s + 1 < NSTG) {
            asm volatile("cp.async.wait_group 1;" ::: "memory");
        } else {
            asm volatile("cp.async.wait_group 0;" ::: "memory");
        }
        __syncthreads();   // publish stage s data; retire stage s-1 reads

        if (s + 2 < NSTG) {
            int nb = buf + 2; if (nb >= 3) nb -= 3;
            issue_load(nb);
        }

        const uint32_t sAb = sbase + buf * STG_BYTES;
        const uint32_t sBb = sAb + 16384;

        #pragma unroll
        for (int ks = 0; ks < 4; ks++) {
            const uint32_t kx = (uint32_t)(ks << 5);
            uint32_t a[2][4];
            #pragma unroll
            for (int mt = 0; mt < 2; mt++) {
                uint32_t ad = sAb + (baseA[mt] ^ kx);
                asm volatile(
                    "ldmatrix.sync.aligned.m8n8.x4.shared.b16 {%0,%1,%2,%3}, [%4];"
                    : "=r"(a[mt][0]), "=r"(a[mt][1]), "=r"(a[mt][2]), "=r"(a[mt][3])
                    : "r"(ad));
            }
            uint32_t bq[4][4];
            #pragma unroll
            for (int nt2 = 0; nt2 < 4; nt2++) {
                uint32_t bd = sBb + (baseB[nt2] ^ kx);
                asm volatile(
                    "ldmatrix.sync.aligned.m8n8.x4.shared.b16 {%0,%1,%2,%3}, [%4];"
                    : "=r"(bq[nt2][0]), "=r"(bq[nt2][1]), "=r"(bq[nt2][2]), "=r"(bq[nt2][3])
                    : "r"(bd));
            }
            #pragma unroll
            for (int mt = 0; mt < 2; mt++)
                #pragma unroll
                for (int nt = 0; nt < 8; nt++) {
                    uint32_t b0 = bq[nt >> 1][(nt & 1) * 2 + 0];
                    uint32_t b1 = bq[nt >> 1][(nt & 1) * 2 + 1];
                    asm volatile(
                        "mma.sync.aligned.m16n8k16.row.col.f32.bf16.bf16.f32 "
                        "{%0,%1,%2,%3}, {%4,%5,%6,%7}, {%8,%9}, {%0,%1,%2,%3};"
                        : "+f"(acc[mt][nt][0]), "+f"(acc[mt][nt][1]),
                          "+f"(acc[mt][nt][2]), "+f"(acc[mt][nt][3])
                        : "r"(a[mt][0]), "r"(a[mt][1]), "r"(a[mt][2]), "r"(a[mt][3]),
                          "r"(b0), "r"(b1));
                }
        }

        // end of an N-chunk: fold acc into per-row top-5, reset acc.
        if (ckc == NKC - 1) {
            const int colBase = ccb * BNC + warpN * 64 + (lane & 3) * 2;
            #pragma unroll
            for (int mt = 0; mt < 2; mt++)
                #pragma unroll
                for (int c2 = 0; c2 < 2; c2++)
                    #pragma unroll
                    for (int nt = 0; nt < 8; nt++)
                        #pragma unroll
                        for (int c1 = 0; c1 < 2; c1++) {
                            float v = acc[mt][nt][c2 * 2 + c1];
                            int col = colBase + nt * 8 + c1;
                            if (col < NROWS && v > t5[mt * 2 + c2][4]) {
                                t5[mt * 2 + c2][4] = v;
                                #pragma unroll
                                for (int j = 4; j > 0; j--) {
                                    if (t5[mt * 2 + c2][j] > t5[mt * 2 + c2][j - 1]) {
                                        float x = t5[mt * 2 + c2][j];
                                        t5[mt * 2 + c2][j] = t5[mt * 2 + c2][j - 1];
                                        t5[mt * 2 + c2][j - 1] = x;
                                    }
                                }
                            }
                        }
            #pragma unroll
            for (int mt = 0; mt < 2; mt++)
                #pragma unroll
                for (int nt = 0; nt < 8; nt++)
                    #pragma unroll
                    for (int c = 0; c < 4; c++) acc[mt][nt][c] = 0.f;
            ckc = 0; ccb++;
        } else {
            ckc++;
        }

        if (++buf == 3) buf = 0;
    }

    // dump per-thread top-5s: row x 8 contributors x 5 (20KB, reuses smem)
    __syncthreads();
    float* dump = (float*)smem;
    const int slot = warpN * 4 + (lane & 3);
    #pragma unroll
    for (int rr = 0; rr < 4; rr++) {
        int row = warpM * 32 + rr * 8 + (lane >> 2);
        #pragma unroll
        for (int j = 0; j < 5; j++)
            dump[row * 40 + slot * 5 + j] = t5[rr][j];
    }
    __syncthreads();

    // final: one thread per row merges 40 candidates -> top-5 mean -> atomicAdd
    if (tid < BM) {
        int gm = mBlock + tid;
        if (gm < MROWS) {
            const float* vals = dump + tid * 40;
            float s0 = -INFINITY, s1 = -INFINITY, s2 = -INFINITY,
                  s3 = -INFINITY, s4 = -INFINITY;
            #pragma unroll
            for (int i = 0; i < 40; i++) {
                float v = vals[i];
                if (v > s4) {
                    s4 = v;
                    if (s4 > s3) { float x = s4; s4 = s3; s3 = x; }
                    if (s3 > s2) { float x = s3; s3 = s2; s2 = x; }
                    if (s2 > s1) { float x = s2; s2 = s1; s1 = x; }
                    if (s1 > s0) { float x = s1; s1 = s0; s0 = x; }
                }
            }
            int q = gm / HW_;
            float val = (s0 + s1 + s2 + s3 + s4) * (1.0f / NK_);
            atomicAdd(&out[(b * Q_ + q) * WAY_ + grp], val);
        }
    }
}

// ---------------------------------------------------------------------------
extern "C" void kernel_launch(void* const* d_in, const int* in_sizes, int n_in,
                              void* d_out, int out_size) {
    const float* input1 = (const float*)d_in[0];   // [2,75,10,10,640]
    const float* input2 = (const float*)d_in[1];   // [2,5,5,10,10,640]
    float* out = (float*)d_out;                    // [2,75,5] = 750

    cudaFuncSetAttribute(fused_gemm_topk_kernel,
                         cudaFuncAttributeMaxDynamicSharedMemorySize, SMEM_TOTAL);

    normalize_kernel<<<(NQTOT + NSTOT + 7) / 8, 256>>>(input1, input2, out);

    dim3 grid((MROWS + BM - 1) / BM, NGRP);        // (59, 10)
    fused_gemm_topk_kernel<<<grid, 256, SMEM_TOTAL>>>(out);
}

// round 9
// speedup vs baseline: 1.2261x; 1.1051x over previous
#include <cuda_runtime.h>
#include <cuda.h>
#include <cuda_bf16.h>
#include <math.h>
#include <stdint.h>

// Problem constants
#define B_    2
#define Q_    75
#define WAY_  5
#define SHOT_ 5
#define HW_   100
#define C_    640
#define NK_   5

#define MROWS (Q_*HW_)        // 7500 query patches per b
#define NROWS (WAY_*HW_)      // 500 support patches per group
#define NGRP  (B_*SHOT_)      // 10 groups
#define NQTOT (B_*MROWS)      // 15000
#define NSTOT (NGRP*NROWS)    // 5000

// Normalized bf16 descriptors (static device scratch — allocation-free)
__device__ __nv_bfloat16 g_q16[(size_t)NQTOT * C_];
__device__ __nv_bfloat16 g_s16[(size_t)NSTOT * C_];

__device__ __forceinline__ uint32_t smem_u32(const void* p) {
    uint32_t a;
    asm("{ .reg .u64 t; cvta.to.shared.u64 t, %1; cvt.u32.u64 %0, t; }"
        : "=r"(a) : "l"(p));
    return a;
}

#define SWZ128(o) ((o) ^ (((o) >> 3) & 0x70))

#define MBARRIER_INIT(addr, cnt) \
    asm volatile("mbarrier.init.shared.b64 [%0], %1;" \
        :: "r"((uint32_t)(addr)), "r"((uint32_t)(cnt)) : "memory")

#define MBARRIER_EXPECT_TX(addr, tx) \
    asm volatile("mbarrier.arrive.expect_tx.shared.b64 _, [%0], %1;" \
        :: "r"((uint32_t)(addr)), "r"((uint32_t)(tx)) : "memory")

#define MBARRIER_WAIT_PARITY(addr, par) do { \
    uint32_t _m = (uint32_t)(addr); uint32_t _p = (uint32_t)(par); uint32_t _d; \
    asm volatile("{ .reg .pred p; mbarrier.try_wait.parity.acquire.cta.shared::cta.b64 p, [%1], %2; selp.b32 %0, 1, 0, p; }" \
        : "=r"(_d) : "r"(_m), "r"(_p) : "memory"); \
    if (!_d) { \
        asm volatile("{ .reg .pred P1; WL_%=: mbarrier.try_wait.parity.acquire.cta.shared::cta.b64 P1, [%0], %1, 0x989680; @P1 bra.uni WD_%=; bra.uni WL_%=; WD_%=: }" \
            :: "r"(_m), "r"(_p) : "memory"); \
    } \
} while (0)

#define TMA3D(smaddr, tmap, cx, cy, cz, mb) \
    asm volatile("cp.async.bulk.tensor.3d.shared::cta.global.tile.mbarrier::complete_tx::bytes " \
        "[%0], [%1, {%2, %3, %4}], [%5];" \
        :: "r"((uint32_t)(smaddr)), "l"(tmap), "r"((int)(cx)), "r"((int)(cy)), \
           "r"((int)(cz)), "r"((uint32_t)(mb)) : "memory")

// ---------------------------------------------------------------------------
// Kernel 1: L2-normalize each 640-dim descriptor, cast to bf16.
// One warp per row (20000 rows). Block 0 also zeroes the 750-float output.
// ---------------------------------------------------------------------------
__global__ void normalize_kernel(const float* __restrict__ q,
                                 const float* __restrict__ s,
                                 float* __restrict__ out) {
    if (blockIdx.x == 0 && threadIdx.x < 250) {
        #pragma unroll
        for (int j = 0; j < 3; j++) out[threadIdx.x + 250 * j] = 0.f;
    }

    int warp = (blockIdx.x * blockDim.x + threadIdx.x) >> 5;
    int lane = threadIdx.x & 31;
    if (warp >= NQTOT + NSTOT) return;

    const float* src;
    __nv_bfloat16* dst;
    if (warp < NQTOT) {
        src = q + (size_t)warp * C_;
        dst = g_q16 + (size_t)warp * C_;
    } else {
        int r = warp - NQTOT;
        src = s + (size_t)r * C_;
        dst = g_s16 + (size_t)r * C_;
    }

    const float4* p4 = (const float4*)src;
    float4 v[5];
    float acc = 0.f;
    #pragma unroll
    for (int t = 0; t < 5; t++) {
        v[t] = p4[lane + 32 * t];
        acc += v[t].x * v[t].x + v[t].y * v[t].y + v[t].z * v[t].z + v[t].w * v[t].w;
    }
    #pragma unroll
    for (int o = 16; o; o >>= 1) acc += __shfl_xor_sync(0xFFFFFFFFu, acc, o);
    float inv = rsqrtf(acc);

    #pragma unroll
    for (int t = 0; t < 5; t++) {
        __nv_bfloat162 lo = __float22bfloat162_rn(make_float2(v[t].x * inv, v[t].y * inv));
        __nv_bfloat162 hi = __float22bfloat162_rn(make_float2(v[t].z * inv, v[t].w * inv));
        uint2 pack;
        pack.x = *(uint32_t*)&lo;
        pack.y = *(uint32_t*)&hi;
        *(uint2*)(dst + (size_t)(lane + 32 * t) * 4) = pack;
    }
}

// ---------------------------------------------------------------------------
// Kernel 2: fused bf16 HMMA GEMM (128 x 512 x 640) + streaming top-5 + reduce.
// grid = (59 M-tiles, 10 groups), 256 threads (8 warps as 4x2), 2 CTAs/SM.
// TMA (cp.async.bulk.tensor) loads with mbarrier pipeline, 3 buffers,
// triple-unrolled stage loop so buffer offsets are immediates.
// ---------------------------------------------------------------------------
#define BM   128
#define BNC  128           // N chunk
#define BK   64            // K chunk (64 bf16 = 128B rows, SW128)
#define NKC  (C_/BK)       // 10
#define NNC  4             // N chunks (covers 512 padded)
#define NSTG (NNC*NKC)     // 40 stages

#define STG_BYTES 32768
#define SMEM_TOTAL (3 * STG_BYTES + 1024 + 64)   // buffers + align pad + mbars

__global__ __launch_bounds__(256, 2)
void fused_gemm_topk_kernel(float* __restrict__ out,
                            const __grid_constant__ CUtensorMap tmA,
                            const __grid_constant__ CUtensorMap tmB) {
    extern __shared__ __align__(1024) char smem[];
    const uint32_t sb   = (smem_u32(smem) + 1023u) & ~1023u;  // 1024-aligned
    const uint32_t mbar = sb + 3 * STG_BYTES;                 // 3 mbarriers
    const int tid   = threadIdx.x;
    const int lane  = tid & 31;
    const int wid   = tid >> 5;
    const int warpM = wid >> 1;      // 0..3
    const int warpN = wid & 1;       // 0..1

    const int mBlock = blockIdx.x * BM;
    const int z   = blockIdx.y;      // b*5 + group
    const int b   = z / SHOT_;
    const int grp = z % SHOT_;

    // ---- mbarrier init + first two TMA loads ----
    if (tid == 0) {
        MBARRIER_INIT(mbar + 0,  1);
        MBARRIER_INIT(mbar + 8,  1);
        MBARRIER_INIT(mbar + 16, 1);
        asm volatile("fence.proxy.async.shared::cta;" ::: "memory");
    }
    __syncthreads();
    if (tid == 0) {
        // stage 0: cb=0, kc=0 -> buf 0
        MBARRIER_EXPECT_TX(mbar + 0, 2 * 16384);
        TMA3D(sb,                 &tmA, 0,  mBlock, b, mbar + 0);
        TMA3D(sb + 16384,         &tmB, 0,  0,      z, mbar + 0);
        // stage 1: cb=0, kc=1 -> buf 1
        MBARRIER_EXPECT_TX(mbar + 8, 2 * 16384);
        TMA3D(sb + STG_BYTES,         &tmA, 64, mBlock, b, mbar + 8);
        TMA3D(sb + STG_BYTES + 16384, &tmB, 64, 0,      z, mbar + 8);
    }

    // ---- ldmatrix bases (XOR with ks<<5 per step) ----
    uint32_t baseA[2], baseB[4];
    #pragma unroll
    for (int mt = 0; mt < 2; mt++) {
        int row = warpM * 32 + mt * 16 + (lane & 15);
        baseA[mt] = SWZ128((uint32_t)(row * 128 + (lane >> 4) * 16));
    }
    {
        int qd = lane >> 3, rr = lane & 7;
        #pragma unroll
        for (int nt2 = 0; nt2 < 4; nt2++) {
            int row = warpN * 64 + nt2 * 16 + (qd >> 1) * 8 + rr;
            baseB[nt2] = SWZ128((uint32_t)(row * 128 + (qd & 1) * 16));
        }
    }

    // running top-5 per owned row: rr -> row = warpM*32 + rr*8 + lane/4
    float t5[4][5];
    #pragma unroll
    for (int r = 0; r < 4; r++)
        #pragma unroll
        for (int j = 0; j < 5; j++) t5[r][j] = -INFINITY;

    float acc[2][8][4];
    #pragma unroll
    for (int mt = 0; mt < 2; mt++)
        #pragma unroll
        for (int nt = 0; nt < 8; nt++)
            #pragma unroll
            for (int c = 0; c < 4; c++) acc[mt][nt][c] = 0.f;

    // compute one stage from buffer at sb + BUFOFF (immediate)
    auto compute_from = [&](const uint32_t bufoff) {
        const uint32_t sAb = sb + bufoff;
        const uint32_t sBb = sAb + 16384;
        #pragma unroll
        for (int ks = 0; ks < 4; ks++) {
            const uint32_t kx = (uint32_t)(ks << 5);
            uint32_t a[2][4];
            #pragma unroll
            for (int mt = 0; mt < 2; mt++) {
                uint32_t ad = sAb + (baseA[mt] ^ kx);
                asm volatile(
                    "ldmatrix.sync.aligned.m8n8.x4.shared.b16 {%0,%1,%2,%3}, [%4];"
                    : "=r"(a[mt][0]), "=r"(a[mt][1]), "=r"(a[mt][2]), "=r"(a[mt][3])
                    : "r"(ad));
            }
            uint32_t bq[4][4];
            #pragma unroll
            for (int nt2 = 0; nt2 < 4; nt2++) {
                uint32_t bd = sBb + (baseB[nt2] ^ kx);
                asm volatile(
                    "ldmatrix.sync.aligned.m8n8.x4.shared.b16 {%0,%1,%2,%3}, [%4];"
                    : "=r"(bq[nt2][0]), "=r"(bq[nt2][1]), "=r"(bq[nt2][2]), "=r"(bq[nt2][3])
                    : "r"(bd));
            }
            #pragma unroll
            for (int mt = 0; mt < 2; mt++)
                #pragma unroll
                for (int nt = 0; nt < 8; nt++) {
                    uint32_t b0 = bq[nt >> 1][(nt & 1) * 2 + 0];
                    uint32_t b1 = bq[nt >> 1][(nt & 1) * 2 + 1];
                    asm volatile(
                        "mma.sync.aligned.m16n8k16.row.col.f32.bf16.bf16.f32 "
                        "{%0,%1,%2,%3}, {%4,%5,%6,%7}, {%8,%9}, {%0,%1,%2,%3};"
                        : "+f"(acc[mt][nt][0]), "+f"(acc[mt][nt][1]),
                          "+f"(acc[mt][nt][2]), "+f"(acc[mt][nt][3])
                        : "r"(a[mt][0]), "r"(a[mt][1]), "r"(a[mt][2]), "r"(a[mt][3]),
                          "r"(b0), "r"(b1));
                }
        }
    };

    int ckc = 0, ccb = 0;          // compute-side kc/cb counters
    auto fold_topk = [&]() {
        const int colBase = ccb * BNC + warpN * 64 + (lane & 3) * 2;
        #pragma unroll
        for (int mt = 0; mt < 2; mt++)
            #pragma unroll
            for (int c2 = 0; c2 < 2; c2++)
                #pragma unroll
                for (int nt = 0; nt < 8; nt++)
                    #pragma unroll
                    for (int c1 = 0; c1 < 2; c1++) {
                        float v = acc[mt][nt][c2 * 2 + c1];
                        int col = colBase + nt * 8 + c1;
                        if (col < NROWS && v > t5[mt * 2 + c2][4]) {
                            t5[mt * 2 + c2][4] = v;
                            #pragma unroll
                            for (int j = 4; j > 0; j--) {
                                if (t5[mt * 2 + c2][j] > t5[mt * 2 + c2][j - 1]) {
                                    float x = t5[mt * 2 + c2][j];
                                    t5[mt * 2 + c2][j] = t5[mt * 2 + c2][j - 1];
                                    t5[mt * 2 + c2][j - 1] = x;
                                }
                            }
                        }
                    }
        #pragma unroll
        for (int mt = 0; mt < 2; mt++)
            #pragma unroll
            for (int nt = 0; nt < 8; nt++)
                #pragma unroll
                for (int c = 0; c < 4; c++) acc[mt][nt][c] = 0.f;
    };

    int s = 0;
    // One stage: sync frees buffer (K+2)%3, tid0 issues TMA for stage s+2,
    // all wait mbar[K] parity PH, compute, maybe fold.
    #define DO_STAGE(K, PH)                                                    \
        do {                                                                   \
            __syncthreads();                                                   \
            if (tid == 0 && s + 2 < NSTG) {                                    \
                const int ns = s + 2;                                          \
                const int nkc = ns % NKC, ncb = ns / NKC;                      \
                const uint32_t dbuf = sb + (((K) + 2) % 3) * STG_BYTES;        \
                const uint32_t nmb = mbar + (((K) + 2) % 3) * 8;               \
                MBARRIER_EXPECT_TX(nmb, 2 * 16384);                            \
                TMA3D(dbuf,         &tmA, nkc * 64, mBlock,    b, nmb);        \
                TMA3D(dbuf + 16384, &tmB, nkc * 64, ncb * 128, z, nmb);        \
            }                                                                  \
            MBARRIER_WAIT_PARITY(mbar + (K) * 8, (PH));                        \
            compute_from((K) * STG_BYTES);                                     \
            if (ckc == NKC - 1) { fold_topk(); ckc = 0; ccb++; } else ckc++;   \
            s++;                                                               \
        } while (0)

    #pragma unroll 1
    for (int t = 0; t < 13; t++) {      // stages 0..38
        const int ph = t & 1;
        DO_STAGE(0, ph);
        DO_STAGE(1, ph);
        DO_STAGE(2, ph);
    }
    DO_STAGE(0, 1);                     // stage 39 (buf0, 14th use -> parity 1)
    #undef DO_STAGE

    // dump per-thread top-5s: row x 8 contributors x 5 (20KB, reuses smem)
    __syncthreads();
    float* dump = (float*)smem;
    const int slot = warpN * 4 + (lane & 3);
    #pragma unroll
    for (int rr = 0; rr < 4; rr++) {
        int row = warpM * 32 + rr * 8 + (lane >> 2);
        #pragma unroll
        for (int j = 0; j < 5; j++)
            dump[row * 40 + slot * 5 + j] = t5[rr][j];
    }
    __syncthreads();

    // final: one thread per row merges 40 candidates -> top-5 mean -> atomicAdd
    if (tid < BM) {
        int gm = mBlock + tid;
        if (gm < MROWS) {
            const float* vals = dump + tid * 40;
            float s0 = -INFINITY, s1 = -INFINITY, s2 = -INFINITY,
                  s3 = -INFINITY, s4 = -INFINITY;
            #pragma unroll
            for (int i = 0; i < 40; i++) {
                float v = vals[i];
                if (v > s4) {
                    s4 = v;
                    if (s4 > s3) { float x = s4; s4 = s3; s3 = x; }
                    if (s3 > s2) { float x = s3; s3 = s2; s2 = x; }
                    if (s2 > s1) { float x = s2; s2 = s1; s1 = x; }
                    if (s1 > s0) { float x = s1; s1 = s0; s0 = x; }
                }
            }
            int q = gm / HW_;
            float val = (s0 + s1 + s2 + s3 + s4) * (1.0f / NK_);
            atomicAdd(&out[(b * Q_ + q) * WAY_ + grp], val);
        }
    }
}

// ---------------------------------------------------------------------------
// Host: build tensormaps (driver entry point fetched via runtime — no -lcuda)
// ---------------------------------------------------------------------------
typedef CUresult (*EncodeTiledFn)(
    CUtensorMap*, CUtensorMapDataType, cuuint32_t, void*,
    const cuuint64_t*, const cuuint64_t*, const cuuint32_t*, const cuuint32_t*,
    CUtensorMapInterleave, CUtensorMapSwizzle, CUtensorMapL2promotion,
    CUtensorMapFloatOOBfill);

extern "C" void kernel_launch(void* const* d_in, const int* in_sizes, int n_in,
                              void* d_out, int out_size) {
    const float* input1 = (const float*)d_in[0];   // [2,75,10,10,640]
    const float* input2 = (const float*)d_in[1];   // [2,5,5,10,10,640]
    float* out = (float*)d_out;                    // [2,75,5] = 750

    // Resolve cuTensorMapEncodeTiled through the runtime (no -lcuda needed)
    void* fn = nullptr;
    cudaDriverEntryPointQueryResult qres;
    cudaGetDriverEntryPoint("cuTensorMapEncodeTiled", &fn,
                            cudaEnableDefault, &qres);
    EncodeTiledFn encode = (EncodeTiledFn)fn;

    void *qptr = nullptr, *sptr = nullptr;
    cudaGetSymbolAddress(&qptr, g_q16);
    cudaGetSymbolAddress(&sptr, g_s16);

    CUtensorMap tmA, tmB;
    {   // A: [2][7500][640] bf16, box [64, 128, 1], SW128
        cuuint64_t dims[3]    = {C_, MROWS, B_};
        cuuint64_t strides[2] = {C_ * 2ull, (cuuint64_t)MROWS * C_ * 2ull};
        cuuint32_t box[3]     = {BK, BM, 1};
        cuuint32_t ones[3]    = {1, 1, 1};
        encode(&tmA, CU_TENSOR_MAP_DATA_TYPE_BFLOAT16, 3, qptr,
               dims, strides, box, ones,
               CU_TENSOR_MAP_INTERLEAVE_NONE, CU_TENSOR_MAP_SWIZZLE_128B,
               CU_TENSOR_MAP_L2_PROMOTION_L2_128B,
               CU_TENSOR_MAP_FLOAT_OOB_FILL_NONE);
    }
    {   // B: [10][500][640] bf16, box [64, 128, 1], SW128 (OOB rows -> 0)
        cuuint64_t dims[3]    = {C_, NROWS, NGRP};
        cuuint64_t strides[2] = {C_ * 2ull, (cuuint64_t)NROWS * C_ * 2ull};
        cuuint32_t box[3]     = {BK, BM, 1};
        cuuint32_t ones[3]    = {1, 1, 1};
        encode(&tmB, CU_TENSOR_MAP_DATA_TYPE_BFLOAT16, 3, sptr,
               dims, strides, box, ones,
               CU_TENSOR_MAP_INTERLEAVE_NONE, CU_TENSOR_MAP_SWIZZLE_128B,
               CU_TENSOR_MAP_L2_PROMOTION_L2_128B,
               CU_TENSOR_MAP_FLOAT_OOB_FILL_NONE);
    }

    cudaFuncSetAttribute(fused_gemm_topk_kernel,
                         cudaFuncAttributeMaxDynamicSharedMemorySize, SMEM_TOTAL);

    normalize_kernel<<<(NQTOT + NSTOT + 7) / 8, 256>>>(input1, input2, out);

    dim3 grid((MROWS + BM - 1) / BM, NGRP);        // (59, 10)
    fused_gemm_topk_kernel<<<grid, 256, SMEM_TOTAL>>>(out, tmA, tmB);
}